// round 1
// baseline (speedup 1.0000x reference)
#include <cuda_runtime.h>
#include <cstdint>

// Problem constants (fixed by the dataset)
#define NN   10000
#define EE   320000
#define BB   2
#define CINN 64
#define HID  128
#define COUT 128
#define TE   128   // edges per block in the edge kernel

// Scratch (device globals: no allocations allowed)
__device__ float g_a_dst[(size_t)NN * HID];        //  5.12 MB
__device__ float g_a_src[(size_t)BB * NN * HID];   // 10.24 MB
__device__ float g_agg  [(size_t)BB * NN * HID];   // 10.24 MB (weighted h2 aggregate)
__device__ float g_den  [NN];

typedef unsigned long long u64;

__device__ __forceinline__ float gelu_f(float v) {
    return 0.5f * v * (1.0f + erff(v * 0.70710678118654752440f));
}
__device__ __forceinline__ u64 pack2(float a) {
    u64 r; asm("mov.b64 %0, {%1, %1};" : "=l"(r) : "f"(a)); return r;
}
__device__ __forceinline__ void ffma2(u64& d, u64 a, u64 b) {
    asm("fma.rn.f32x2 %0, %1, %2, %0;" : "+l"(d) : "l"(a), "l"(b));
}
__device__ __forceinline__ float2 unpack2(u64 v) {
    float2 f; asm("mov.b64 {%0, %1}, %2;" : "=f"(f.x), "=f"(f.y) : "l"(v)); return f;
}

// ---------------------------------------------------------------------------
// Zero the aggregation buffers (d_out is poisoned; agg/den must start at 0)
// ---------------------------------------------------------------------------
__global__ void zero_kernel() {
    const size_t i = (size_t)blockIdx.x * blockDim.x + threadIdx.x;
    if (i < (size_t)BB * NN * HID) g_agg[i] = 0.0f;
    if (i < NN)                    g_den[i] = 0.0f;
}

// ---------------------------------------------------------------------------
// den[n] = sum of edge_weights into dst n
// ---------------------------------------------------------------------------
__global__ void den_kernel(const int* __restrict__ eidx, const float* __restrict__ ew) {
    const int e = blockIdx.x * blockDim.x + threadIdx.x;
    if (e < EE) atomicAdd(&g_den[eidx[EE + e]], ew[e]);
}

// ---------------------------------------------------------------------------
// Per-node precompute:
//   a_dst[n]   = pos[n] @ W1[0:3]
//   a_src[b,n] = pos[n] @ W1[3:6] + x[b,n] @ W1[6:70] + b1
//   out[b,n]   = x[b,n] @ Ws + bs   (skip path, written first; final adds)
// One block per (b,n), 128 threads (thread = output channel).
// ---------------------------------------------------------------------------
__global__ void precompute_kernel(const float* __restrict__ x, const float* __restrict__ pos,
                                  const float* __restrict__ W1, const float* __restrict__ b1,
                                  const float* __restrict__ Ws, const float* __restrict__ bs,
                                  float* __restrict__ out) {
    const int blk = blockIdx.x;          // b*NN + n
    const int b   = blk / NN;
    const int n   = blk - b * NN;
    const int t   = threadIdx.x;         // 0..127
    __shared__ float xr[CINN];
    __shared__ float p3[3];
    if (t < CINN) xr[t] = x[(size_t)blk * CINN + t];
    if (t < 3)    p3[t] = pos[n * 3 + t];
    __syncthreads();

    float s = b1[t];
#pragma unroll
    for (int j = 0; j < 3; ++j) s += p3[j] * W1[(3 + j) * HID + t];
#pragma unroll 8
    for (int c = 0; c < CINN; ++c) s += xr[c] * W1[(6 + c) * HID + t];
    g_a_src[(size_t)blk * HID + t] = s;

    if (b == 0) {
        float d = p3[0] * W1[0 * HID + t] + p3[1] * W1[1 * HID + t] + p3[2] * W1[2 * HID + t];
        g_a_dst[(size_t)n * HID + t] = d;
    }

    float sk = bs[t];
#pragma unroll 8
    for (int c = 0; c < CINN; ++c) sk += xr[c] * Ws[c * COUT + t];
    out[(size_t)blk * COUT + t] = sk;
}

// ---------------------------------------------------------------------------
// Edge kernel: per tile of TE=128 edges (x batch):
//   h1 = gelu(a_dst[dst] + a_src[b,src])         (filled transposed [k][m] in smem)
//   acc = h1 @ W2                                 (register-tiled, f32x2 FFMA)
//   s[b,dst] += w_e * gelu(acc + b2)              (red.global.add.v4.f32)
// 256 threads, thread tile = 8 edges x 8 cols. smem = 128 KB (h tile + W2).
// ---------------------------------------------------------------------------
__global__ void __launch_bounds__(256, 1)
edge_kernel(const int* __restrict__ eidx, const float* __restrict__ ew,
            const float* __restrict__ W2, const float* __restrict__ b2) {
    extern __shared__ float sm[];
    float* h_s = sm;               // [128][128]  h1 transposed: h_s[k][m]
    float* w_s = sm + HID * HID;   // [128][128]  W2[k][n]
    const int tid = threadIdx.x;
    const int e0  = blockIdx.x * TE;
    const int b   = blockIdx.y;
    const int* __restrict__ srcp = eidx;
    const int* __restrict__ dstp = eidx + EE;

    // Stage W2 (16384 floats, coalesced float4)
    {
        const float4* w4 = (const float4*)W2;
        float4* s4 = (float4*)w_s;
#pragma unroll
        for (int i = 0; i < 16; ++i) s4[tid + i * 256] = w4[tid + i * 256];
    }

    // Fill h1 tile transposed. Each warp owns 16 edges; lane pairs split k so
    // a pair reads contiguous 32B from the same row (full-sector gathers).
    {
        const int w = tid >> 5, l = tid & 31;
        const int m = w * 16 + (l >> 1);
        const int e = e0 + m;
        const int s = srcp[e];
        const int d = dstp[e];
        const float4* pd4 = (const float4*)(g_a_dst + (size_t)d * HID);
        const float4* ps4 = (const float4*)(g_a_src + ((size_t)b * NN + s) * HID);
        const int p = l & 1;
#pragma unroll
        for (int k8 = 0; k8 < 16; ++k8) {
            const int kq = k8 * 2 + p;         // float4 index along k
            float4 A  = pd4[kq];
            float4 Bv = ps4[kq];
            const int k = kq * 4;
            h_s[(k + 0) * HID + m] = gelu_f(A.x + Bv.x);
            h_s[(k + 1) * HID + m] = gelu_f(A.y + Bv.y);
            h_s[(k + 2) * HID + m] = gelu_f(A.z + Bv.z);
            h_s[(k + 3) * HID + m] = gelu_f(A.w + Bv.w);
        }
    }
    __syncthreads();

    // Register-tiled GEMM: thread (tm,tn) computes edges tm*8..+7,
    // cols {tn*4..+3} and {64+tn*4..+3}. A-reads broadcast within half-warp.
    const int tn = tid & 15;
    const int tm = tid >> 4;
    u64 acc[8][4];
#pragma unroll
    for (int i = 0; i < 8; ++i)
#pragma unroll
        for (int g = 0; g < 4; ++g) acc[i][g] = 0ull;

#pragma unroll 8
    for (int k = 0; k < 128; ++k) {
        const float* hr = h_s + k * HID + tm * 8;
        const float4 A0 = *(const float4*)hr;
        const float4 A1 = *(const float4*)(hr + 4);
        const float* wr = w_s + k * HID + tn * 4;
        const ulonglong2 B0 = *(const ulonglong2*)wr;          // n = tn*4 .. +3
        const ulonglong2 B1 = *(const ulonglong2*)(wr + 64);   // n = 64+tn*4 .. +3
        const float av[8] = {A0.x, A0.y, A0.z, A0.w, A1.x, A1.y, A1.z, A1.w};
#pragma unroll
        for (int i = 0; i < 8; ++i) {
            const u64 a2 = pack2(av[i]);
            ffma2(acc[i][0], a2, B0.x);
            ffma2(acc[i][1], a2, B0.y);
            ffma2(acc[i][2], a2, B1.x);
            ffma2(acc[i][3], a2, B1.y);
        }
    }

    // Epilogue: gelu(acc + b2) * w_e, 16B vector reductions into g_agg
    const float4 b2v0 = *(const float4*)(b2 + tn * 4);
    const float4 b2v1 = *(const float4*)(b2 + 64 + tn * 4);
#pragma unroll
    for (int i = 0; i < 8; ++i) {
        const int m = tm * 8 + i;
        const int e = e0 + m;
        const float wgt = ew[e];
        const int d = dstp[e];
        float* base = g_agg + ((size_t)b * NN + d) * HID;
        {
            const float2 v0 = unpack2(acc[i][0]);
            const float2 v1 = unpack2(acc[i][1]);
            const float r0 = wgt * gelu_f(v0.x + b2v0.x);
            const float r1 = wgt * gelu_f(v0.y + b2v0.y);
            const float r2 = wgt * gelu_f(v1.x + b2v0.z);
            const float r3 = wgt * gelu_f(v1.y + b2v0.w);
            asm volatile("red.global.add.v4.f32 [%0], {%1,%2,%3,%4};"
                         :: "l"(base + tn * 4), "f"(r0), "f"(r1), "f"(r2), "f"(r3)
                         : "memory");
        }
        {
            const float2 v0 = unpack2(acc[i][2]);
            const float2 v1 = unpack2(acc[i][3]);
            const float r0 = wgt * gelu_f(v0.x + b2v1.x);
            const float r1 = wgt * gelu_f(v0.y + b2v1.y);
            const float r2 = wgt * gelu_f(v1.x + b2v1.z);
            const float r3 = wgt * gelu_f(v1.y + b2v1.w);
            asm volatile("red.global.add.v4.f32 [%0], {%1,%2,%3,%4};"
                         :: "l"(base + 64 + tn * 4), "f"(r0), "f"(r1), "f"(r2), "f"(r3)
                         : "memory");
        }
    }
}

// ---------------------------------------------------------------------------
// Final: out[b,n] += (s[b,n] @ W3 + den[n]*b3) / (den[n] + eps)
// One block per (b,n); 128 threads; W3 stays L1-resident (64 KB).
// ---------------------------------------------------------------------------
__global__ void final_kernel(const float* __restrict__ W3, const float* __restrict__ b3,
                             float* __restrict__ out) {
    __shared__ float s_s[HID];
    const int blk = blockIdx.x;       // b*NN + n
    const int n   = blk % NN;
    const int c   = threadIdx.x;
    s_s[c] = g_agg[(size_t)blk * HID + c];
    __syncthreads();
    const float den = g_den[n];
    float acc = den * b3[c];
#pragma unroll 8
    for (int k = 0; k < HID; ++k) acc += s_s[k] * W3[k * COUT + c];
    out[(size_t)blk * COUT + c] += acc / (den + 1e-12f);
}

// ---------------------------------------------------------------------------
extern "C" void kernel_launch(void* const* d_in, const int* in_sizes, int n_in,
                              void* d_out, int out_size) {
    const float* x   = (const float*)d_in[0];
    const float* pos = (const float*)d_in[1];
    const int*   ei  = (const int*)  d_in[2];
    const float* ew  = (const float*)d_in[3];
    const float* W1  = (const float*)d_in[4];
    const float* b1  = (const float*)d_in[5];
    const float* W2  = (const float*)d_in[6];
    const float* b2  = (const float*)d_in[7];
    const float* W3  = (const float*)d_in[8];
    const float* b3  = (const float*)d_in[9];
    const float* Ws  = (const float*)d_in[10];
    const float* bs  = (const float*)d_in[11];
    float* out = (float*)d_out;

    cudaFuncSetAttribute(edge_kernel, cudaFuncAttributeMaxDynamicSharedMemorySize,
                         2 * HID * HID * (int)sizeof(float));

    zero_kernel<<<(BB * NN * HID + 255) / 256, 256>>>();
    precompute_kernel<<<BB * NN, HID>>>(x, pos, W1, b1, Ws, bs, out);
    den_kernel<<<(EE + 255) / 256, 256>>>(ei, ew);
    edge_kernel<<<dim3(EE / TE, BB), 256, 2 * HID * HID * sizeof(float)>>>(ei, ew, W2, b2);
    final_kernel<<<BB * NN, HID>>>(W3, b3, out);
}